// round 6
// baseline (speedup 1.0000x reference)
#include <cuda_runtime.h>
#include <cuda_bf16.h>
#include <math.h>
#include <stdint.h>

// Problem constants (fixed shapes)
#define NN 50000
#define EE 800000
#define DIN 256
#define HH 128
#define RR 8
#define HEADS 8
#define DHH 16
#define OUTC 3

// ---------------- scratch (device globals; no allocation allowed) ----------
__device__ float g_S[(size_t)NN * RR * HH];
__device__ float g_h1[(size_t)NN * HH];
__device__ float g_h2[(size_t)NN * HH];
__device__ float g_h3[(size_t)NN * HH];
__device__ float g_z[(size_t)NN * HH];
__device__ float g_deg[(size_t)NN * RR];
__device__ float g_asrc[(size_t)NN * HEADS];
__device__ float g_atgt[(size_t)NN * HEADS];
__device__ unsigned g_amax[(size_t)NN * HEADS];
__device__ float g_denom[(size_t)NN * HEADS];
__device__ float g_alpha[(size_t)EE * HEADS];
__device__ float g_outun[(size_t)NN * HH];

// ---------------- helpers ----------------
__device__ __forceinline__ void red4(float* p, float a, float b, float c, float d) {
    asm volatile("red.global.add.v4.f32 [%0], {%1,%2,%3,%4};"
                 :: "l"(p), "f"(a), "f"(b), "f"(c), "f"(d) : "memory");
}
__device__ __forceinline__ unsigned enc_f(float f) {
    unsigned u = __float_as_uint(f);
    return (u & 0x80000000u) ? ~u : (u | 0x80000000u);
}
__device__ __forceinline__ float dec_f(unsigned k) {
    unsigned u = (k & 0x80000000u) ? (k & 0x7FFFFFFFu) : ~k;
    return __uint_as_float(u);
}
#define ENC_NEG_INF 0x007FFFFFu

// split float pair (x = k even, y = k odd) into packed bf16x2 hi + lo
__device__ __forceinline__ void split2(float x, float y, uint32_t& hp, uint32_t& lp) {
    __nv_bfloat16 xh = __float2bfloat16(x);
    __nv_bfloat16 yh = __float2bfloat16(y);
    float xr = x - __bfloat162float(xh);
    float yr = y - __bfloat162float(yh);
    __nv_bfloat16 xl = __float2bfloat16(xr);
    __nv_bfloat16 yl = __float2bfloat16(yr);
    hp = ((uint32_t)__bfloat16_as_ushort(yh) << 16) | (uint32_t)__bfloat16_as_ushort(xh);
    lp = ((uint32_t)__bfloat16_as_ushort(yl) << 16) | (uint32_t)__bfloat16_as_ushort(xl);
}

__device__ __forceinline__ void mma_bf16(float& c0, float& c1, float& c2, float& c3,
                                         uint32_t a0, uint32_t a1, uint32_t a2, uint32_t a3,
                                         uint32_t b0, uint32_t b1) {
    asm volatile("mma.sync.aligned.m16n8k16.row.col.f32.bf16.bf16.f32 "
                 "{%0,%1,%2,%3}, {%4,%5,%6,%7}, {%8,%9}, {%0,%1,%2,%3};"
                 : "+f"(c0), "+f"(c1), "+f"(c2), "+f"(c3)
                 : "r"(a0), "r"(a1), "r"(a2), "r"(a3), "r"(b0), "r"(b1));
}

// ---------------- fill kernels ----------------
__global__ void fill_f4(float4* p, int n4, float v) {
    float4 q = make_float4(v, v, v, v);
    for (int i = blockIdx.x * blockDim.x + threadIdx.x; i < n4; i += gridDim.x * blockDim.x)
        p[i] = q;
}
__global__ void fill_u4(uint4* p, int n4, unsigned v) {
    uint4 q = make_uint4(v, v, v, v);
    for (int i = blockIdx.x * blockDim.x + threadIdx.x; i < n4; i += gridDim.x * blockDim.x)
        p[i] = q;
}

// -------- bf16x3 pipelined tensor-core GEMM: C[M,128] = A@B (+A2@B2)+bias ---
// fp32-accurate via A=Ah+Al, B=Bh+Bl (bf16 splits); C = AhBh + AhBl + AlBh.
// MODE 0: plain, A[M,K] row-major, B[K,128]
// MODE 1: RGCN,  A = S[M,1024] scaled by invdeg per 128-col block, B = W[1024,128],
//                A2 = h[M,128], B2 = root[128,128], Ksplit=1024, K=1152
// 8 warps (4M x 2N), BM=BN=128, BK=16, warp tile 32x64 (2 mt x 8 nt x 3 MMA).
// Double-buffered smem + register prefetch of next k-slice; 1 sync/iter.
template<int MODE, bool RELU>
__global__ __launch_bounds__(256) void gemm_bf16x3(
    const float* __restrict__ A, const float* __restrict__ B,
    const float* __restrict__ A2, const float* __restrict__ B2,
    const float* __restrict__ invdeg, const float* __restrict__ bias,
    float* __restrict__ C, int M, int K, int Ksplit)
{
    constexpr int LDSW = 136;  // word stride: bank = (8*kp + idx) % 32, bijective
    __shared__ uint32_t As_h[2][8][LDSW], As_l[2][8][LDSW];   // [buf][kpair][row]
    __shared__ uint32_t Bs_h[2][8][LDSW], Bs_l[2][8][LDSW];   // [buf][kpair][col]

    const int tid = threadIdx.x;
    const int lane = tid & 31;
    const int warp = tid >> 5;
    const int warp_m = warp & 3;   // 32-row slab
    const int warp_n = warp >> 2;  // 64-col slab
    const int bm = blockIdx.x * 128;

    const int a_row = tid & 127;
    const int a_k8 = (tid >> 7) << 3;     // k offset 0 or 8
    const int b_kp = tid >> 5;            // kpair 0..7
    const int b_c4 = (tid & 31) << 2;     // col 0..124 step 4

    const int row_g = bm + a_row;
    const bool row_ok = (row_g < M);

    const int tig = lane & 3;
    const int gid = lane >> 2;

    float c[2][8][4];
#pragma unroll
    for (int i = 0; i < 2; i++)
#pragma unroll
        for (int j = 0; j < 8; j++)
#pragma unroll
            for (int q = 0; q < 4; q++) c[i][j][q] = 0.0f;

    float va[8];
    float4 rb0, rb1;

    // ---- global load of k-slice k0 into registers ----
    auto loadA = [&](int k0) {
        int kk = k0 + a_k8;
#pragma unroll
        for (int i = 0; i < 8; i++) va[i] = 0.f;
        if (row_ok) {
            float4 v0, v1;
            if (MODE == 1) {
                if (kk < Ksplit) {
                    const float* p = A + (size_t)row_g * Ksplit + kk;
                    v0 = *(const float4*)p;
                    v1 = *(const float4*)(p + 4);
                    float sc = invdeg[row_g * RR + (kk >> 7)];
                    v0.x *= sc; v0.y *= sc; v0.z *= sc; v0.w *= sc;
                    v1.x *= sc; v1.y *= sc; v1.z *= sc; v1.w *= sc;
                } else {
                    const float* p = A2 + (size_t)row_g * HH + (kk - Ksplit);
                    v0 = *(const float4*)p;
                    v1 = *(const float4*)(p + 4);
                }
            } else {
                const float* p = A + (size_t)row_g * K + kk;
                v0 = *(const float4*)p;
                v1 = *(const float4*)(p + 4);
            }
            va[0] = v0.x; va[1] = v0.y; va[2] = v0.z; va[3] = v0.w;
            va[4] = v1.x; va[5] = v1.y; va[6] = v1.z; va[7] = v1.w;
        }
    };
    auto loadB = [&](int k0) {
        int kr0 = k0 + 2 * b_kp;
        int kr1 = kr0 + 1;
        const float* p0 = (MODE == 1 && kr0 >= Ksplit)
            ? (B2 + (size_t)(kr0 - Ksplit) * 128 + b_c4)
            : (B + (size_t)kr0 * 128 + b_c4);
        const float* p1 = (MODE == 1 && kr1 >= Ksplit)
            ? (B2 + (size_t)(kr1 - Ksplit) * 128 + b_c4)
            : (B + (size_t)kr1 * 128 + b_c4);
        rb0 = *(const float4*)p0;
        rb1 = *(const float4*)p1;
    };
    // ---- split registers -> smem[buf] ----
    auto store = [&](int buf) {
        int kp0 = a_k8 >> 1;
#pragma unroll
        for (int i = 0; i < 4; i++) {
            uint32_t hp, lp;
            split2(va[2 * i], va[2 * i + 1], hp, lp);
            As_h[buf][kp0 + i][a_row] = hp;
            As_l[buf][kp0 + i][a_row] = lp;
        }
        uint32_t hp[4], lp[4];
        split2(rb0.x, rb1.x, hp[0], lp[0]);
        split2(rb0.y, rb1.y, hp[1], lp[1]);
        split2(rb0.z, rb1.z, hp[2], lp[2]);
        split2(rb0.w, rb1.w, hp[3], lp[3]);
        *(uint4*)&Bs_h[buf][b_kp][b_c4] = make_uint4(hp[0], hp[1], hp[2], hp[3]);
        *(uint4*)&Bs_l[buf][b_kp][b_c4] = make_uint4(lp[0], lp[1], lp[2], lp[3]);
    };
    // ---- MMA from smem[buf] ----
    auto compute = [&](int buf) {
        uint32_t ah[2][4], al[2][4];
#pragma unroll
        for (int mt = 0; mt < 2; mt++) {
            int r = warp_m * 32 + mt * 16 + gid;
            ah[mt][0] = As_h[buf][tig][r];     ah[mt][1] = As_h[buf][tig][r + 8];
            ah[mt][2] = As_h[buf][tig + 4][r]; ah[mt][3] = As_h[buf][tig + 4][r + 8];
            al[mt][0] = As_l[buf][tig][r];     al[mt][1] = As_l[buf][tig][r + 8];
            al[mt][2] = As_l[buf][tig + 4][r]; al[mt][3] = As_l[buf][tig + 4][r + 8];
        }
#pragma unroll
        for (int half = 0; half < 2; half++) {
            uint32_t bh[4][2], bl[4][2];
#pragma unroll
            for (int n4 = 0; n4 < 4; n4++) {
                int cc = warp_n * 64 + (half * 4 + n4) * 8 + gid;
                bh[n4][0] = Bs_h[buf][tig][cc]; bh[n4][1] = Bs_h[buf][tig + 4][cc];
                bl[n4][0] = Bs_l[buf][tig][cc]; bl[n4][1] = Bs_l[buf][tig + 4][cc];
            }
#pragma unroll
            for (int mt = 0; mt < 2; mt++)
#pragma unroll
                for (int n4 = 0; n4 < 4; n4++) {
                    int nt = half * 4 + n4;
                    mma_bf16(c[mt][nt][0], c[mt][nt][1], c[mt][nt][2], c[mt][nt][3],
                             ah[mt][0], ah[mt][1], ah[mt][2], ah[mt][3],
                             bh[n4][0], bh[n4][1]);
                    mma_bf16(c[mt][nt][0], c[mt][nt][1], c[mt][nt][2], c[mt][nt][3],
                             ah[mt][0], ah[mt][1], ah[mt][2], ah[mt][3],
                             bl[n4][0], bl[n4][1]);
                    mma_bf16(c[mt][nt][0], c[mt][nt][1], c[mt][nt][2], c[mt][nt][3],
                             al[mt][0], al[mt][1], al[mt][2], al[mt][3],
                             bh[n4][0], bh[n4][1]);
                }
        }
    };

    // ---- pipelined main loop ----
    const int NIT = K / 16;
    loadA(0); loadB(0);
    store(0);
    __syncthreads();
#pragma unroll 1
    for (int it = 0; it < NIT; it++) {
        int buf = it & 1;
        bool more = (it + 1 < NIT);
        if (more) { loadA((it + 1) * 16); loadB((it + 1) * 16); }
        compute(buf);
        if (more) {
            store(buf ^ 1);
            __syncthreads();
        }
    }

    // ---- epilogue ----
    const int er0 = bm + warp_m * 32 + gid;
    const int ec0 = warp_n * 64 + (tig << 1);
#pragma unroll
    for (int mt = 0; mt < 2; mt++) {
#pragma unroll
        for (int half = 0; half < 2; half++) {
            int row = er0 + mt * 16 + half * 8;
            if (row >= M) continue;
#pragma unroll
            for (int nt = 0; nt < 8; nt++) {
                int col = ec0 + nt * 8;
                float v0 = c[mt][nt][half * 2 + 0];
                float v1 = c[mt][nt][half * 2 + 1];
                if (bias) { v0 += bias[col]; v1 += bias[col + 1]; }
                if (RELU) { v0 = fmaxf(v0, 0.f); v1 = fmaxf(v1, 0.f); }
                *(float2*)(C + (size_t)row * HH + col) = make_float2(v0, v1);
            }
        }
    }
}

// ---------------- RGCN scatter: warp per edge ----------------
__global__ void rgcn_scatter(const int* __restrict__ src, const int* __restrict__ tgt,
                             const int* __restrict__ et, const float* __restrict__ h,
                             float* __restrict__ S, float* __restrict__ deg, int E)
{
    int w = (blockIdx.x * blockDim.x + threadIdx.x) >> 5;
    int lane = threadIdx.x & 31;
    if (w >= E) return;
    int s = src[w], t = tgt[w], r = et[w];
    float4 v = ((const float4*)(h + (size_t)s * HH))[lane];
    float* dst = S + (size_t)t * (RR * HH) + r * HH + lane * 4;
    red4(dst, v.x, v.y, v.z, v.w);
    if (lane == 0) atomicAdd(deg + t * RR + r, 1.0f);
}

__global__ void make_invdeg(float* deg, int n) {
    int i = blockIdx.x * blockDim.x + threadIdx.x;
    if (i < n) deg[i] = 1.0f / fmaxf(deg[i], 1.0f);
}

// ---------------- GAT ----------------
__global__ void att_node(const float* __restrict__ z, const float* __restrict__ att,
                         float* __restrict__ asrc, float* __restrict__ atgt, int n)
{
    int i = blockIdx.x * blockDim.x + threadIdx.x;
    if (i >= n * HEADS) return;
    int node = i >> 3, hd = i & 7;
    const float* zp = z + (size_t)node * HH + hd * DHH;
    const float* al = att + hd * (2 * DHH);
    float sa = 0.f, sb = 0.f;
#pragma unroll
    for (int d = 0; d < DHH; d++) {
        float zv = zp[d];
        sa += zv * al[d];
        sb += zv * al[DHH + d];
    }
    asrc[i] = sa;
    atgt[i] = sb;
}

__global__ void gat_pass1(const int* __restrict__ src, const int* __restrict__ tgt,
                          const float* __restrict__ asrc, const float* __restrict__ atgt,
                          float* __restrict__ alpha, unsigned* __restrict__ amax, int E)
{
    int e = blockIdx.x * blockDim.x + threadIdx.x;
    if (e >= E) return;
    int s = src[e], t = tgt[e];
    float4 s0 = ((const float4*)(asrc + (size_t)s * HEADS))[0];
    float4 s1 = ((const float4*)(asrc + (size_t)s * HEADS))[1];
    float4 t0 = ((const float4*)(atgt + (size_t)t * HEADS))[0];
    float4 t1 = ((const float4*)(atgt + (size_t)t * HEADS))[1];
    float a[8] = { s0.x + t0.x, s0.y + t0.y, s0.z + t0.z, s0.w + t0.w,
                   s1.x + t1.x, s1.y + t1.y, s1.z + t1.z, s1.w + t1.w };
#pragma unroll
    for (int hd = 0; hd < 8; hd++) a[hd] = a[hd] > 0.f ? a[hd] : 0.2f * a[hd];
    ((float4*)(alpha + (size_t)e * HEADS))[0] = make_float4(a[0], a[1], a[2], a[3]);
    ((float4*)(alpha + (size_t)e * HEADS))[1] = make_float4(a[4], a[5], a[6], a[7]);
#pragma unroll
    for (int hd = 0; hd < 8; hd++) atomicMax(amax + t * HEADS + hd, enc_f(a[hd]));
}

__global__ void gat_pass2(const int* __restrict__ src, const int* __restrict__ tgt,
                          const float* __restrict__ alpha, const unsigned* __restrict__ amax,
                          const float* __restrict__ z, float* __restrict__ denom,
                          float* __restrict__ outun, int E)
{
    int w = (blockIdx.x * blockDim.x + threadIdx.x) >> 5;
    int lane = threadIdx.x & 31;
    if (w >= E) return;
    int s = src[w], t = tgt[w];
    int head = lane >> 2;
    float al = alpha[(size_t)w * HEADS + head];
    float am = dec_f(amax[t * HEADS + head]);
    float ex = __expf(al - am);
    if ((lane & 3) == 0) atomicAdd(denom + t * HEADS + head, ex);
    float4 zv = ((const float4*)(z + (size_t)s * HH))[lane];
    red4(outun + (size_t)t * HH + lane * 4, zv.x * ex, zv.y * ex, zv.z * ex, zv.w * ex);
}

// finalize: gat-normalize + bg, then 128x3 projection, log_softmax. Warp per node.
__global__ void finalize(const float* __restrict__ outun, const float* __restrict__ denom,
                         const float* __restrict__ bg, const float* __restrict__ Wf,
                         const float* __restrict__ bf, float* __restrict__ out, int n)
{
    int w = (blockIdx.x * blockDim.x + threadIdx.x) >> 5;
    int lane = threadIdx.x & 31;
    if (w >= n) return;
    float4 g = ((const float4*)(outun + (size_t)w * HH))[lane];
    int head = lane >> 2;
    float dn = denom[w * HEADS + head];
    float inv = 1.0f / fmaxf(dn, 1e-16f);
    float4 bgv = ((const float4*)bg)[lane];
    float gv[4] = { g.x * inv + bgv.x, g.y * inv + bgv.y,
                    g.z * inv + bgv.z, g.w * inv + bgv.w };
    float a0 = 0.f, a1 = 0.f, a2 = 0.f;
    int j0 = lane * 4;
#pragma unroll
    for (int c = 0; c < 4; c++) {
        int j = j0 + c;
        a0 += gv[c] * Wf[j * OUTC + 0];
        a1 += gv[c] * Wf[j * OUTC + 1];
        a2 += gv[c] * Wf[j * OUTC + 2];
    }
#pragma unroll
    for (int off = 16; off > 0; off >>= 1) {
        a0 += __shfl_xor_sync(0xFFFFFFFFu, a0, off);
        a1 += __shfl_xor_sync(0xFFFFFFFFu, a1, off);
        a2 += __shfl_xor_sync(0xFFFFFFFFu, a2, off);
    }
    if (lane == 0) {
        float l0 = a0 + bf[0], l1 = a1 + bf[1], l2 = a2 + bf[2];
        float m = fmaxf(l0, fmaxf(l1, l2));
        float lse = m + logf(expf(l0 - m) + expf(l1 - m) + expf(l2 - m));
        out[(size_t)w * OUTC + 0] = l0 - lse;
        out[(size_t)w * OUTC + 1] = l1 - lse;
        out[(size_t)w * OUTC + 2] = l2 - lse;
    }
}

// ---------------- launch ----------------
extern "C" void kernel_launch(void* const* d_in, const int* in_sizes, int n_in,
                              void* d_out, int out_size)
{
    const float* x     = (const float*)d_in[0];
    const int*   ei    = (const int*)d_in[1];
    const int*   etype = (const int*)d_in[2];
    const float* Wp    = (const float*)d_in[3];
    const float* bp    = (const float*)d_in[4];
    const float* W1    = (const float*)d_in[5];
    const float* root1 = (const float*)d_in[6];
    const float* b1    = (const float*)d_in[7];
    const float* W2    = (const float*)d_in[8];
    const float* root2 = (const float*)d_in[9];
    const float* b2    = (const float*)d_in[10];
    const float* Wg    = (const float*)d_in[11];
    const float* att   = (const float*)d_in[12];
    const float* bg    = (const float*)d_in[13];
    const float* Wf    = (const float*)d_in[14];
    const float* bf    = (const float*)d_in[15];
    float* out = (float*)d_out;

    const int* src = ei;
    const int* tgt = ei + EE;

    float *S, *h1, *h2, *h3, *z, *deg, *asrc, *atgt, *denom, *alpha, *outun;
    unsigned* amax;
    cudaGetSymbolAddress((void**)&S, g_S);
    cudaGetSymbolAddress((void**)&h1, g_h1);
    cudaGetSymbolAddress((void**)&h2, g_h2);
    cudaGetSymbolAddress((void**)&h3, g_h3);
    cudaGetSymbolAddress((void**)&z, g_z);
    cudaGetSymbolAddress((void**)&deg, g_deg);
    cudaGetSymbolAddress((void**)&asrc, g_asrc);
    cudaGetSymbolAddress((void**)&atgt, g_atgt);
    cudaGetSymbolAddress((void**)&denom, g_denom);
    cudaGetSymbolAddress((void**)&alpha, g_alpha);
    cudaGetSymbolAddress((void**)&outun, g_outun);
    cudaGetSymbolAddress((void**)&amax, g_amax);

    const int gemmGrid = (NN + 127) / 128;   // 391
    const int scatGrid = (EE + 7) / 8;
    const int fillGrid = 4096;

    // ---- projection: h1 = x @ Wp + bp
    gemm_bf16x3<0, false><<<gemmGrid, 256>>>(x, Wp, nullptr, nullptr, nullptr, bp, h1, NN, DIN, DIN);

    // ---- RGCN layer 1 -> h2
    fill_f4<<<fillGrid, 256>>>((float4*)S, NN * RR * HH / 4, 0.f);
    fill_f4<<<64, 256>>>((float4*)deg, NN * RR / 4, 0.f);
    rgcn_scatter<<<scatGrid, 256>>>(src, tgt, etype, h1, S, deg, EE);
    make_invdeg<<<(NN * RR + 255) / 256, 256>>>(deg, NN * RR);
    gemm_bf16x3<1, true><<<gemmGrid, 256>>>(S, W1, h1, root1, deg, b1, h2, NN, RR * HH + HH, RR * HH);

    // ---- RGCN layer 2 -> h3
    fill_f4<<<fillGrid, 256>>>((float4*)S, NN * RR * HH / 4, 0.f);
    fill_f4<<<64, 256>>>((float4*)deg, NN * RR / 4, 0.f);
    rgcn_scatter<<<scatGrid, 256>>>(src, tgt, etype, h2, S, deg, EE);
    make_invdeg<<<(NN * RR + 255) / 256, 256>>>(deg, NN * RR);
    gemm_bf16x3<1, true><<<gemmGrid, 256>>>(S, W2, h2, root2, deg, b2, h3, NN, RR * HH + HH, RR * HH);

    // ---- GAT
    gemm_bf16x3<0, false><<<gemmGrid, 256>>>(h3, Wg, nullptr, nullptr, nullptr, nullptr, z, NN, HH, HH);
    att_node<<<(NN * HEADS + 255) / 256, 256>>>(z, att, asrc, atgt, NN);
    fill_u4<<<64, 256>>>((uint4*)amax, NN * HEADS / 4, ENC_NEG_INF);
    fill_f4<<<64, 256>>>((float4*)denom, NN * HEADS / 4, 0.f);
    fill_f4<<<512, 256>>>((float4*)outun, NN * HH / 4, 0.f);
    gat_pass1<<<(EE + 255) / 256, 256>>>(src, tgt, asrc, atgt, alpha, amax, EE);
    gat_pass2<<<scatGrid, 256>>>(src, tgt, alpha, amax, z, denom, outun, EE);

    // ---- finalize
    finalize<<<(NN + 7) / 8, 256>>>(outun, denom, bg, Wf, bf, out, NN);
}

// round 7
// speedup vs baseline: 1.0513x; 1.0513x over previous
#include <cuda_runtime.h>
#include <cuda_bf16.h>
#include <math.h>
#include <stdint.h>

// Problem constants (fixed shapes)
#define NN 50000
#define EE 800000
#define DIN 256
#define HH 128
#define RR 8
#define HEADS 8
#define DHH 16
#define OUTC 3

// ---------------- scratch (device globals; no allocation allowed) ----------
__device__ float g_S[(size_t)NN * RR * HH];
__device__ float g_h1[(size_t)NN * HH];
__device__ float g_h2[(size_t)NN * HH];
__device__ float g_h3[(size_t)NN * HH];
__device__ float g_z[(size_t)NN * HH];
__device__ float g_deg[(size_t)NN * RR];
__device__ float g_asrc[(size_t)NN * HEADS];
__device__ float g_atgt[(size_t)NN * HEADS];
__device__ unsigned g_amax[(size_t)NN * HEADS];
__device__ float g_denom[(size_t)NN * HEADS];
__device__ float g_alpha[(size_t)EE * HEADS];
__device__ float g_outun[(size_t)NN * HH];

// ---------------- helpers ----------------
__device__ __forceinline__ void red4(float* p, float a, float b, float c, float d) {
    asm volatile("red.global.add.v4.f32 [%0], {%1,%2,%3,%4};"
                 :: "l"(p), "f"(a), "f"(b), "f"(c), "f"(d) : "memory");
}
__device__ __forceinline__ unsigned enc_f(float f) {
    unsigned u = __float_as_uint(f);
    return (u & 0x80000000u) ? ~u : (u | 0x80000000u);
}
__device__ __forceinline__ float dec_f(unsigned k) {
    unsigned u = (k & 0x80000000u) ? (k & 0x7FFFFFFFu) : ~k;
    return __uint_as_float(u);
}
#define ENC_NEG_INF 0x007FFFFFu

// split float pair (x = k even, y = k odd) into packed bf16x2 hi + lo
__device__ __forceinline__ void split2(float x, float y, uint32_t& hp, uint32_t& lp) {
    __nv_bfloat16 xh = __float2bfloat16(x);
    __nv_bfloat16 yh = __float2bfloat16(y);
    float xr = x - __bfloat162float(xh);
    float yr = y - __bfloat162float(yh);
    __nv_bfloat16 xl = __float2bfloat16(xr);
    __nv_bfloat16 yl = __float2bfloat16(yr);
    hp = ((uint32_t)__bfloat16_as_ushort(yh) << 16) | (uint32_t)__bfloat16_as_ushort(xh);
    lp = ((uint32_t)__bfloat16_as_ushort(yl) << 16) | (uint32_t)__bfloat16_as_ushort(xl);
}

__device__ __forceinline__ void mma_bf16(float& c0, float& c1, float& c2, float& c3,
                                         uint32_t a0, uint32_t a1, uint32_t a2, uint32_t a3,
                                         uint32_t b0, uint32_t b1) {
    asm volatile("mma.sync.aligned.m16n8k16.row.col.f32.bf16.bf16.f32 "
                 "{%0,%1,%2,%3}, {%4,%5,%6,%7}, {%8,%9}, {%0,%1,%2,%3};"
                 : "+f"(c0), "+f"(c1), "+f"(c2), "+f"(c3)
                 : "r"(a0), "r"(a1), "r"(a2), "r"(a3), "r"(b0), "r"(b1));
}

// ---------------- fill kernels ----------------
__global__ void fill_f4(float4* p, int n4, float v) {
    float4 q = make_float4(v, v, v, v);
    for (int i = blockIdx.x * blockDim.x + threadIdx.x; i < n4; i += gridDim.x * blockDim.x)
        p[i] = q;
}
__global__ void fill_u4(uint4* p, int n4, unsigned v) {
    uint4 q = make_uint4(v, v, v, v);
    for (int i = blockIdx.x * blockDim.x + threadIdx.x; i < n4; i += gridDim.x * blockDim.x)
        p[i] = q;
}

// -------- bf16x3 tensor-core GEMM: C[M,128] = A@B (+A2@B2) + bias ----------
// fp32-accurate via A=Ah+Al, B=Bh+Bl (bf16 splits); C = AhBh + AhBl + AlBh.
// MODE 0: plain, A[M,K] row-major, B[K,128]
// MODE 1: RGCN,  A = S[M,1024] scaled by invdeg per 128-col block, B = W[1024,128],
//                A2 = h[M,128], B2 = root[128,128], Ksplit=1024, K=1152
// 8 warps (4M x 2N), BM=BN=128, BK=16, warp tile 32x64 (2 mt x 8 nt x 3 MMA).
// Single-buffer smem (17.4KB) + __launch_bounds__(256,2) -> 2 CTAs/SM.
template<int MODE, bool RELU>
__global__ __launch_bounds__(256, 2) void gemm_bf16x3(
    const float* __restrict__ A, const float* __restrict__ B,
    const float* __restrict__ A2, const float* __restrict__ B2,
    const float* __restrict__ invdeg, const float* __restrict__ bias,
    float* __restrict__ C, int M, int K, int Ksplit)
{
    constexpr int LDSW = 136;  // word stride: bank = (8*kp + idx) % 32, bijective
    __shared__ uint32_t As_h[8][LDSW], As_l[8][LDSW];   // [kpair][row]
    __shared__ uint32_t Bs_h[8][LDSW], Bs_l[8][LDSW];   // [kpair][col]

    const int tid = threadIdx.x;
    const int lane = tid & 31;
    const int warp = tid >> 5;
    const int warp_m = warp & 3;   // 32-row slab
    const int warp_n = warp >> 2;  // 64-col slab
    const int bm = blockIdx.x * 128;

    const int a_row = tid & 127;
    const int a_k8 = (tid >> 7) << 3;
    const int b_kp = tid >> 5;
    const int b_c4 = (tid & 31) << 2;

    const int row_g = bm + a_row;
    const bool row_ok = (row_g < M);

    const int tig = lane & 3;
    const int gid = lane >> 2;

    float c[2][8][4];
#pragma unroll
    for (int i = 0; i < 2; i++)
#pragma unroll
        for (int j = 0; j < 8; j++)
#pragma unroll
            for (int q = 0; q < 4; q++) c[i][j][q] = 0.0f;

#pragma unroll 1
    for (int k0 = 0; k0 < K; k0 += 16) {
        // ---- load + split A tile ----
        {
            int kk = k0 + a_k8;
            float v[8] = {0.f, 0.f, 0.f, 0.f, 0.f, 0.f, 0.f, 0.f};
            if (row_ok) {
                float4 v0, v1;
                if (MODE == 1) {
                    if (kk < Ksplit) {
                        const float* p = A + (size_t)row_g * Ksplit + kk;
                        v0 = *(const float4*)p;
                        v1 = *(const float4*)(p + 4);
                        float sc = invdeg[row_g * RR + (kk >> 7)];
                        v0.x *= sc; v0.y *= sc; v0.z *= sc; v0.w *= sc;
                        v1.x *= sc; v1.y *= sc; v1.z *= sc; v1.w *= sc;
                    } else {
                        const float* p = A2 + (size_t)row_g * HH + (kk - Ksplit);
                        v0 = *(const float4*)p;
                        v1 = *(const float4*)(p + 4);
                    }
                } else {
                    const float* p = A + (size_t)row_g * K + kk;
                    v0 = *(const float4*)p;
                    v1 = *(const float4*)(p + 4);
                }
                v[0] = v0.x; v[1] = v0.y; v[2] = v0.z; v[3] = v0.w;
                v[4] = v1.x; v[5] = v1.y; v[6] = v1.z; v[7] = v1.w;
            }
            int kp0 = a_k8 >> 1;
#pragma unroll
            for (int i = 0; i < 4; i++) {
                uint32_t hp, lp;
                split2(v[2 * i], v[2 * i + 1], hp, lp);
                As_h[kp0 + i][a_row] = hp;
                As_l[kp0 + i][a_row] = lp;
            }
        }
        // ---- load + split B tile ----
        {
            int kr0 = k0 + 2 * b_kp;
            int kr1 = kr0 + 1;
            const float* p0 = (MODE == 1 && kr0 >= Ksplit)
                ? (B2 + (size_t)(kr0 - Ksplit) * 128 + b_c4)
                : (B + (size_t)kr0 * 128 + b_c4);
            const float* p1 = (MODE == 1 && kr1 >= Ksplit)
                ? (B2 + (size_t)(kr1 - Ksplit) * 128 + b_c4)
                : (B + (size_t)kr1 * 128 + b_c4);
            float4 r0 = *(const float4*)p0;
            float4 r1 = *(const float4*)p1;
            uint32_t hp[4], lp[4];
            split2(r0.x, r1.x, hp[0], lp[0]);
            split2(r0.y, r1.y, hp[1], lp[1]);
            split2(r0.z, r1.z, hp[2], lp[2]);
            split2(r0.w, r1.w, hp[3], lp[3]);
            *(uint4*)&Bs_h[b_kp][b_c4] = make_uint4(hp[0], hp[1], hp[2], hp[3]);
            *(uint4*)&Bs_l[b_kp][b_c4] = make_uint4(lp[0], lp[1], lp[2], lp[3]);
        }
        __syncthreads();

        // ---- fragments + MMA (B frags in two nt-halves to cut live regs) ----
        uint32_t ah[2][4], al[2][4];
#pragma unroll
        for (int mt = 0; mt < 2; mt++) {
            int r = warp_m * 32 + mt * 16 + gid;
            ah[mt][0] = As_h[tig][r];     ah[mt][1] = As_h[tig][r + 8];
            ah[mt][2] = As_h[tig + 4][r]; ah[mt][3] = As_h[tig + 4][r + 8];
            al[mt][0] = As_l[tig][r];     al[mt][1] = As_l[tig][r + 8];
            al[mt][2] = As_l[tig + 4][r]; al[mt][3] = As_l[tig + 4][r + 8];
        }
#pragma unroll
        for (int half = 0; half < 2; half++) {
            uint32_t bh[4][2], bl[4][2];
#pragma unroll
            for (int n4 = 0; n4 < 4; n4++) {
                int cc = warp_n * 64 + (half * 4 + n4) * 8 + gid;
                bh[n4][0] = Bs_h[tig][cc]; bh[n4][1] = Bs_h[tig + 4][cc];
                bl[n4][0] = Bs_l[tig][cc]; bl[n4][1] = Bs_l[tig + 4][cc];
            }
#pragma unroll
            for (int mt = 0; mt < 2; mt++)
#pragma unroll
                for (int n4 = 0; n4 < 4; n4++) {
                    int nt = half * 4 + n4;
                    mma_bf16(c[mt][nt][0], c[mt][nt][1], c[mt][nt][2], c[mt][nt][3],
                             ah[mt][0], ah[mt][1], ah[mt][2], ah[mt][3],
                             bh[n4][0], bh[n4][1]);
                    mma_bf16(c[mt][nt][0], c[mt][nt][1], c[mt][nt][2], c[mt][nt][3],
                             ah[mt][0], ah[mt][1], ah[mt][2], ah[mt][3],
                             bl[n4][0], bl[n4][1]);
                    mma_bf16(c[mt][nt][0], c[mt][nt][1], c[mt][nt][2], c[mt][nt][3],
                             al[mt][0], al[mt][1], al[mt][2], al[mt][3],
                             bh[n4][0], bh[n4][1]);
                }
        }
        __syncthreads();
    }

    // ---- epilogue ----
    const int er0 = bm + warp_m * 32 + gid;
    const int ec0 = warp_n * 64 + (tig << 1);
#pragma unroll
    for (int mt = 0; mt < 2; mt++) {
#pragma unroll
        for (int half = 0; half < 2; half++) {
            int row = er0 + mt * 16 + half * 8;
            if (row >= M) continue;
#pragma unroll
            for (int nt = 0; nt < 8; nt++) {
                int col = ec0 + nt * 8;
                float v0 = c[mt][nt][half * 2 + 0];
                float v1 = c[mt][nt][half * 2 + 1];
                if (bias) { v0 += bias[col]; v1 += bias[col + 1]; }
                if (RELU) { v0 = fmaxf(v0, 0.f); v1 = fmaxf(v1, 0.f); }
                *(float2*)(C + (size_t)row * HH + col) = make_float2(v0, v1);
            }
        }
    }
}

// ---------------- RGCN scatter: warp per edge ----------------
__global__ void rgcn_scatter(const int* __restrict__ src, const int* __restrict__ tgt,
                             const int* __restrict__ et, const float* __restrict__ h,
                             float* __restrict__ S, float* __restrict__ deg, int E)
{
    int w = (blockIdx.x * blockDim.x + threadIdx.x) >> 5;
    int lane = threadIdx.x & 31;
    if (w >= E) return;
    int s = src[w], t = tgt[w], r = et[w];
    float4 v = ((const float4*)(h + (size_t)s * HH))[lane];
    float* dst = S + (size_t)t * (RR * HH) + r * HH + lane * 4;
    red4(dst, v.x, v.y, v.z, v.w);
    if (lane == 0) atomicAdd(deg + t * RR + r, 1.0f);
}

__global__ void make_invdeg(float* deg, int n) {
    int i = blockIdx.x * blockDim.x + threadIdx.x;
    if (i < n) deg[i] = 1.0f / fmaxf(deg[i], 1.0f);
}

// ---------------- GAT ----------------
__global__ void att_node(const float* __restrict__ z, const float* __restrict__ att,
                         float* __restrict__ asrc, float* __restrict__ atgt, int n)
{
    int i = blockIdx.x * blockDim.x + threadIdx.x;
    if (i >= n * HEADS) return;
    int node = i >> 3, hd = i & 7;
    const float* zp = z + (size_t)node * HH + hd * DHH;
    const float* al = att + hd * (2 * DHH);
    float sa = 0.f, sb = 0.f;
#pragma unroll
    for (int d = 0; d < DHH; d++) {
        float zv = zp[d];
        sa += zv * al[d];
        sb += zv * al[DHH + d];
    }
    asrc[i] = sa;
    atgt[i] = sb;
}

__global__ void gat_pass1(const int* __restrict__ src, const int* __restrict__ tgt,
                          const float* __restrict__ asrc, const float* __restrict__ atgt,
                          float* __restrict__ alpha, unsigned* __restrict__ amax, int E)
{
    int e = blockIdx.x * blockDim.x + threadIdx.x;
    if (e >= E) return;
    int s = src[e], t = tgt[e];
    float4 s0 = ((const float4*)(asrc + (size_t)s * HEADS))[0];
    float4 s1 = ((const float4*)(asrc + (size_t)s * HEADS))[1];
    float4 t0 = ((const float4*)(atgt + (size_t)t * HEADS))[0];
    float4 t1 = ((const float4*)(atgt + (size_t)t * HEADS))[1];
    float a[8] = { s0.x + t0.x, s0.y + t0.y, s0.z + t0.z, s0.w + t0.w,
                   s1.x + t1.x, s1.y + t1.y, s1.z + t1.z, s1.w + t1.w };
#pragma unroll
    for (int hd = 0; hd < 8; hd++) a[hd] = a[hd] > 0.f ? a[hd] : 0.2f * a[hd];
    ((float4*)(alpha + (size_t)e * HEADS))[0] = make_float4(a[0], a[1], a[2], a[3]);
    ((float4*)(alpha + (size_t)e * HEADS))[1] = make_float4(a[4], a[5], a[6], a[7]);
#pragma unroll
    for (int hd = 0; hd < 8; hd++) atomicMax(amax + t * HEADS + hd, enc_f(a[hd]));
}

__global__ void gat_pass2(const int* __restrict__ src, const int* __restrict__ tgt,
                          const float* __restrict__ alpha, const unsigned* __restrict__ amax,
                          const float* __restrict__ z, float* __restrict__ denom,
                          float* __restrict__ outun, int E)
{
    int w = (blockIdx.x * blockDim.x + threadIdx.x) >> 5;
    int lane = threadIdx.x & 31;
    if (w >= E) return;
    int s = src[w], t = tgt[w];
    int head = lane >> 2;
    float al = alpha[(size_t)w * HEADS + head];
    float am = dec_f(amax[t * HEADS + head]);
    float ex = __expf(al - am);
    if ((lane & 3) == 0) atomicAdd(denom + t * HEADS + head, ex);
    float4 zv = ((const float4*)(z + (size_t)s * HH))[lane];
    red4(outun + (size_t)t * HH + lane * 4, zv.x * ex, zv.y * ex, zv.z * ex, zv.w * ex);
}

// finalize: gat-normalize + bg, then 128x3 projection, log_softmax. Warp per node.
__global__ void finalize(const float* __restrict__ outun, const float* __restrict__ denom,
                         const float* __restrict__ bg, const float* __restrict__ Wf,
                         const float* __restrict__ bf, float* __restrict__ out, int n)
{
    int w = (blockIdx.x * blockDim.x + threadIdx.x) >> 5;
    int lane = threadIdx.x & 31;
    if (w >= n) return;
    float4 g = ((const float4*)(outun + (size_t)w * HH))[lane];
    int head = lane >> 2;
    float dn = denom[w * HEADS + head];
    float inv = 1.0f / fmaxf(dn, 1e-16f);
    float4 bgv = ((const float4*)bg)[lane];
    float gv[4] = { g.x * inv + bgv.x, g.y * inv + bgv.y,
                    g.z * inv + bgv.z, g.w * inv + bgv.w };
    float a0 = 0.f, a1 = 0.f, a2 = 0.f;
    int j0 = lane * 4;
#pragma unroll
    for (int c = 0; c < 4; c++) {
        int j = j0 + c;
        a0 += gv[c] * Wf[j * OUTC + 0];
        a1 += gv[c] * Wf[j * OUTC + 1];
        a2 += gv[c] * Wf[j * OUTC + 2];
    }
#pragma unroll
    for (int off = 16; off > 0; off >>= 1) {
        a0 += __shfl_xor_sync(0xFFFFFFFFu, a0, off);
        a1 += __shfl_xor_sync(0xFFFFFFFFu, a1, off);
        a2 += __shfl_xor_sync(0xFFFFFFFFu, a2, off);
    }
    if (lane == 0) {
        float l0 = a0 + bf[0], l1 = a1 + bf[1], l2 = a2 + bf[2];
        float m = fmaxf(l0, fmaxf(l1, l2));
        float lse = m + logf(expf(l0 - m) + expf(l1 - m) + expf(l2 - m));
        out[(size_t)w * OUTC + 0] = l0 - lse;
        out[(size_t)w * OUTC + 1] = l1 - lse;
        out[(size_t)w * OUTC + 2] = l2 - lse;
    }
}

// ---------------- launch ----------------
extern "C" void kernel_launch(void* const* d_in, const int* in_sizes, int n_in,
                              void* d_out, int out_size)
{
    const float* x     = (const float*)d_in[0];
    const int*   ei    = (const int*)d_in[1];
    const int*   etype = (const int*)d_in[2];
    const float* Wp    = (const float*)d_in[3];
    const float* bp    = (const float*)d_in[4];
    const float* W1    = (const float*)d_in[5];
    const float* root1 = (const float*)d_in[6];
    const float* b1    = (const float*)d_in[7];
    const float* W2    = (const float*)d_in[8];
    const float* root2 = (const float*)d_in[9];
    const float* b2    = (const float*)d_in[10];
    const float* Wg    = (const float*)d_in[11];
    const float* att   = (const float*)d_in[12];
    const float* bg    = (const float*)d_in[13];
    const float* Wf    = (const float*)d_in[14];
    const float* bf    = (const float*)d_in[15];
    float* out = (float*)d_out;

    const int* src = ei;
    const int* tgt = ei + EE;

    float *S, *h1, *h2, *h3, *z, *deg, *asrc, *atgt, *denom, *alpha, *outun;
    unsigned* amax;
    cudaGetSymbolAddress((void**)&S, g_S);
    cudaGetSymbolAddress((void**)&h1, g_h1);
    cudaGetSymbolAddress((void**)&h2, g_h2);
    cudaGetSymbolAddress((void**)&h3, g_h3);
    cudaGetSymbolAddress((void**)&z, g_z);
    cudaGetSymbolAddress((void**)&deg, g_deg);
    cudaGetSymbolAddress((void**)&asrc, g_asrc);
    cudaGetSymbolAddress((void**)&atgt, g_atgt);
    cudaGetSymbolAddress((void**)&denom, g_denom);
    cudaGetSymbolAddress((void**)&alpha, g_alpha);
    cudaGetSymbolAddress((void**)&outun, g_outun);
    cudaGetSymbolAddress((void**)&amax, g_amax);

    const int gemmGrid = (NN + 127) / 128;   // 391
    const int scatGrid = (EE + 7) / 8;
    const int fillGrid = 4096;

    // ---- projection: h1 = x @ Wp + bp
    gemm_bf16x3<0, false><<<gemmGrid, 256>>>(x, Wp, nullptr, nullptr, nullptr, bp, h1, NN, DIN, DIN);

    // ---- RGCN layer 1 -> h2
    fill_f4<<<fillGrid, 256>>>((float4*)S, NN * RR * HH / 4, 0.f);
    fill_f4<<<64, 256>>>((float4*)deg, NN * RR / 4, 0.f);
    rgcn_scatter<<<scatGrid, 256>>>(src, tgt, etype, h1, S, deg, EE);
    make_invdeg<<<(NN * RR + 255) / 256, 256>>>(deg, NN * RR);
    gemm_bf16x3<1, true><<<gemmGrid, 256>>>(S, W1, h1, root1, deg, b1, h2, NN, RR * HH + HH, RR * HH);

    // ---- RGCN layer 2 -> h3
    fill_f4<<<fillGrid, 256>>>((float4*)S, NN * RR * HH / 4, 0.f);
    fill_f4<<<64, 256>>>((float4*)deg, NN * RR / 4, 0.f);
    rgcn_scatter<<<scatGrid, 256>>>(src, tgt, etype, h2, S, deg, EE);
    make_invdeg<<<(NN * RR + 255) / 256, 256>>>(deg, NN * RR);
    gemm_bf16x3<1, true><<<gemmGrid, 256>>>(S, W2, h2, root2, deg, b2, h3, NN, RR * HH + HH, RR * HH);

    // ---- GAT
    gemm_bf16x3<0, false><<<gemmGrid, 256>>>(h3, Wg, nullptr, nullptr, nullptr, nullptr, z, NN, HH, HH);
    att_node<<<(NN * HEADS + 255) / 256, 256>>>(z, att, asrc, atgt, NN);
    fill_u4<<<64, 256>>>((uint4*)amax, NN * HEADS / 4, ENC_NEG_INF);
    fill_f4<<<64, 256>>>((float4*)denom, NN * HEADS / 4, 0.f);
    fill_f4<<<512, 256>>>((float4*)outun, NN * HH / 4, 0.f);
    gat_pass1<<<(EE + 255) / 256, 256>>>(src, tgt, asrc, atgt, alpha, amax, EE);
    gat_pass2<<<scatGrid, 256>>>(src, tgt, alpha, amax, z, denom, outun, EE);

    // ---- finalize
    finalize<<<(NN + 7) / 8, 256>>>(outun, denom, bg, Wf, bf, out, NN);
}

// round 9
// speedup vs baseline: 1.1928x; 1.1346x over previous
#include <cuda_runtime.h>
#include <cuda_bf16.h>
#include <math.h>
#include <stdint.h>

// Problem constants (fixed shapes)
#define NN 50000
#define EE 800000
#define DIN 256
#define HH 128
#define RR 8
#define HEADS 8
#define DHH 16
#define OUTC 3
#define KW_H 64     // HH/2 packed words per row
#define KW_X 128    // DIN/2 packed words per row

// ---------------- scratch (device globals; no allocation allowed) ----------
__device__ float    g_Y[(size_t)NN * RR * HH];      // [n][r*128+j]
__device__ float    g_agg[(size_t)NN * HH];
__device__ uint32_t g_xhi[(size_t)NN * KW_X], g_xlo[(size_t)NN * KW_X];
__device__ uint32_t g_hAhi[(size_t)NN * KW_H], g_hAlo[(size_t)NN * KW_H];
__device__ uint32_t g_hBhi[(size_t)NN * KW_H], g_hBlo[(size_t)NN * KW_H];
__device__ uint32_t g_w1hi[9 * KW_H * HH], g_w1lo[9 * KW_H * HH];   // W1[0..7] + root1
__device__ uint32_t g_w2hi[9 * KW_H * HH], g_w2lo[9 * KW_H * HH];   // W2[0..7] + root2
__device__ uint32_t g_wphi[KW_X * HH], g_wplo[KW_X * HH];
__device__ uint32_t g_wghi[KW_H * HH], g_wglo[KW_H * HH];
__device__ float    g_z[(size_t)NN * HH];
__device__ float    g_deg[(size_t)NN * RR];          // degree -> invdeg in place
__device__ float    g_asrc[(size_t)NN * HEADS];
__device__ float    g_atgt[(size_t)NN * HEADS];
__device__ unsigned g_amax[(size_t)NN * HEADS];
__device__ float    g_denom[(size_t)NN * HEADS];
__device__ float    g_alpha[(size_t)EE * HEADS];
__device__ float    g_outun[(size_t)NN * HH];

// ---------------- helpers ----------------
__device__ __forceinline__ void red4(float* p, float a, float b, float c, float d) {
    asm volatile("red.global.add.v4.f32 [%0], {%1,%2,%3,%4};"
                 :: "l"(p), "f"(a), "f"(b), "f"(c), "f"(d) : "memory");
}
__device__ __forceinline__ unsigned enc_f(float f) {
    unsigned u = __float_as_uint(f);
    return (u & 0x80000000u) ? ~u : (u | 0x80000000u);
}
__device__ __forceinline__ float dec_f(unsigned k) {
    unsigned u = (k & 0x80000000u) ? (k & 0x7FFFFFFFu) : ~k;
    return __uint_as_float(u);
}
#define ENC_NEG_INF 0x007FFFFFu

// split float pair (x = k even, y = k odd) into packed bf16x2 hi + lo
__device__ __forceinline__ void split2(float x, float y, uint32_t& hp, uint32_t& lp) {
    __nv_bfloat16 xh = __float2bfloat16(x);
    __nv_bfloat16 yh = __float2bfloat16(y);
    float xr = x - __bfloat162float(xh);
    float yr = y - __bfloat162float(yh);
    __nv_bfloat16 xl = __float2bfloat16(xr);
    __nv_bfloat16 yl = __float2bfloat16(yr);
    hp = ((uint32_t)__bfloat16_as_ushort(yh) << 16) | (uint32_t)__bfloat16_as_ushort(xh);
    lp = ((uint32_t)__bfloat16_as_ushort(yl) << 16) | (uint32_t)__bfloat16_as_ushort(xl);
}

__device__ __forceinline__ void mma_bf16(float& c0, float& c1, float& c2, float& c3,
                                         uint32_t a0, uint32_t a1, uint32_t a2, uint32_t a3,
                                         uint32_t b0, uint32_t b1) {
    asm volatile("mma.sync.aligned.m16n8k16.row.col.f32.bf16.bf16.f32 "
                 "{%0,%1,%2,%3}, {%4,%5,%6,%7}, {%8,%9}, {%0,%1,%2,%3};"
                 : "+f"(c0), "+f"(c1), "+f"(c2), "+f"(c3)
                 : "r"(a0), "r"(a1), "r"(a2), "r"(a3), "r"(b0), "r"(b1));
}

// ---------------- fill / pack / split kernels ----------------
__global__ void fill_f4(float4* p, int n4, float v) {
    float4 q = make_float4(v, v, v, v);
    for (int i = blockIdx.x * blockDim.x + threadIdx.x; i < n4; i += gridDim.x * blockDim.x)
        p[i] = q;
}
__global__ void fill_u4(uint4* p, int n4, unsigned v) {
    uint4 q = make_uint4(v, v, v, v);
    for (int i = blockIdx.x * blockDim.x + threadIdx.x; i < n4; i += gridDim.x * blockDim.x)
        p[i] = q;
}

// pack B chunks: fp32 [2*Kw x 128] row-major -> [Kw][128] hi/lo bf16x2 (pairs along K)
// blockIdx.y selects chunk; last chunk uses srcRoot if non-null.
__global__ void pack_b(const float* __restrict__ srcW, const float* __restrict__ srcRoot,
                       uint32_t* __restrict__ dhi, uint32_t* __restrict__ dlo, int Kw) {
    int y = blockIdx.y;
    const float* src = (srcRoot != nullptr && y == (int)gridDim.y - 1)
                       ? srcRoot : srcW + (size_t)y * Kw * 2 * HH;
    int i = blockIdx.x * blockDim.x + threadIdx.x;
    if (i >= Kw * HH) return;
    int kp = i >> 7, n = i & 127;
    float a = src[(size_t)(2 * kp) * HH + n];
    float b = src[(size_t)(2 * kp + 1) * HH + n];
    uint32_t hp, lp; split2(a, b, hp, lp);
    dhi[(size_t)y * Kw * HH + i] = hp;
    dlo[(size_t)y * Kw * HH + i] = lp;
}

// split a contiguous row-major fp32 matrix into packed hi/lo words (pairs along row)
__global__ void split_mat(const float* __restrict__ src, uint32_t* __restrict__ dhi,
                          uint32_t* __restrict__ dlo, int nwords) {
    int i = blockIdx.x * blockDim.x + threadIdx.x;
    if (i >= nwords) return;
    float2 v = ((const float2*)src)[i];
    uint32_t hp, lp; split2(v.x, v.y, hp, lp);
    dhi[i] = hp; dlo[i] = lp;
}

// ---------------- packed-operand bf16x3 tensor-core GEMM ----------------
// C[M,128] = A@B where A,B are pre-split hi/lo bf16x2 word arrays.
// A: [M][Kw] words (pairs along K). B: [Kw][128] words per chunk; chunk = blockIdx.y.
// EPI 0: f32 out Cf (ld=HH). EPI 1: packed hi/lo out + bias. EPI 2: rgcn dual
//        (blockIdx.y<8 -> Y at col-offset by*128, ld=RR*HH; by==8 -> Cagg, ld=HH).
// 8 warps (4M x 2N), BM=BN=128, BK=16 (8 words), warp tile 32x64, 3 MMAs/tile.
template<int EPI>
__global__ __launch_bounds__(256, 2) void gemm_pk(
    const uint32_t* __restrict__ Ahi, const uint32_t* __restrict__ Alo,
    const uint32_t* __restrict__ Bhi_base, const uint32_t* __restrict__ Blo_base,
    const float* __restrict__ bias,
    float* __restrict__ Cf, float* __restrict__ Cagg,
    uint32_t* __restrict__ Chi, uint32_t* __restrict__ Clo,
    int M, int Kw)
{
    constexpr int LDSW = 136;
    __shared__ uint32_t As_h[8][LDSW], As_l[8][LDSW];   // [kpair][row]
    __shared__ uint32_t Bs_h[8][LDSW], Bs_l[8][LDSW];   // [kpair][col]

    const int tid = threadIdx.x;
    const int lane = tid & 31;
    const int warp = tid >> 5;
    const int warp_m = warp & 3;
    const int warp_n = warp >> 2;
    const int bm = blockIdx.x * 128;
    const int by = blockIdx.y;

    const uint32_t* Bhi = Bhi_base + (size_t)by * Kw * HH;
    const uint32_t* Blo = Blo_base + (size_t)by * Kw * HH;

    const int a_row = tid & 127;
    const int a_kq = (tid >> 7) << 2;     // word offset 0 or 4
    const int b_kp = tid >> 5;            // kpair row 0..7
    const int b_n4 = (tid & 31) << 2;     // col 0..124 step 4

    const int row_g = bm + a_row;
    const bool row_ok = (row_g < M);

    const int tig = lane & 3;
    const int gid = lane >> 2;

    float c[2][8][4];
#pragma unroll
    for (int i = 0; i < 2; i++)
#pragma unroll
        for (int j = 0; j < 8; j++)
#pragma unroll
            for (int q = 0; q < 4; q++) c[i][j][q] = 0.0f;

#pragma unroll 1
    for (int kp0 = 0; kp0 < Kw; kp0 += 8) {
        // ---- A tile: straight packed loads ----
        uint4 vh = make_uint4(0, 0, 0, 0), vl = make_uint4(0, 0, 0, 0);
        if (row_ok) {
            vh = *(const uint4*)(Ahi + (size_t)row_g * Kw + kp0 + a_kq);
            vl = *(const uint4*)(Alo + (size_t)row_g * Kw + kp0 + a_kq);
        }
        As_h[a_kq + 0][a_row] = vh.x; As_h[a_kq + 1][a_row] = vh.y;
        As_h[a_kq + 2][a_row] = vh.z; As_h[a_kq + 3][a_row] = vh.w;
        As_l[a_kq + 0][a_row] = vl.x; As_l[a_kq + 1][a_row] = vl.y;
        As_l[a_kq + 2][a_row] = vl.z; As_l[a_kq + 3][a_row] = vl.w;
        // ---- B tile ----
        {
            uint4 bh = *(const uint4*)(Bhi + (size_t)(kp0 + b_kp) * HH + b_n4);
            uint4 bl = *(const uint4*)(Blo + (size_t)(kp0 + b_kp) * HH + b_n4);
            *(uint4*)&Bs_h[b_kp][b_n4] = bh;
            *(uint4*)&Bs_l[b_kp][b_n4] = bl;
        }
        __syncthreads();

        uint32_t ah[2][4], al[2][4];
#pragma unroll
        for (int mt = 0; mt < 2; mt++) {
            int r = warp_m * 32 + mt * 16 + gid;
            ah[mt][0] = As_h[tig][r];     ah[mt][1] = As_h[tig][r + 8];
            ah[mt][2] = As_h[tig + 4][r]; ah[mt][3] = As_h[tig + 4][r + 8];
            al[mt][0] = As_l[tig][r];     al[mt][1] = As_l[tig][r + 8];
            al[mt][2] = As_l[tig + 4][r]; al[mt][3] = As_l[tig + 4][r + 8];
        }
#pragma unroll
        for (int half = 0; half < 2; half++) {
            uint32_t bh[4][2], bl[4][2];
#pragma unroll
            for (int n4 = 0; n4 < 4; n4++) {
                int cc = warp_n * 64 + (half * 4 + n4) * 8 + gid;
                bh[n4][0] = Bs_h[tig][cc]; bh[n4][1] = Bs_h[tig + 4][cc];
                bl[n4][0] = Bs_l[tig][cc]; bl[n4][1] = Bs_l[tig + 4][cc];
            }
#pragma unroll
            for (int mt = 0; mt < 2; mt++)
#pragma unroll
                for (int n4 = 0; n4 < 4; n4++) {
                    int nt = half * 4 + n4;
                    mma_bf16(c[mt][nt][0], c[mt][nt][1], c[mt][nt][2], c[mt][nt][3],
                             ah[mt][0], ah[mt][1], ah[mt][2], ah[mt][3],
                             bh[n4][0], bh[n4][1]);
                    mma_bf16(c[mt][nt][0], c[mt][nt][1], c[mt][nt][2], c[mt][nt][3],
                             ah[mt][0], ah[mt][1], ah[mt][2], ah[mt][3],
                             bl[n4][0], bl[n4][1]);
                    mma_bf16(c[mt][nt][0], c[mt][nt][1], c[mt][nt][2], c[mt][nt][3],
                             al[mt][0], al[mt][1], al[mt][2], al[mt][3],
                             bh[n4][0], bh[n4][1]);
                }
        }
        __syncthreads();
    }

    // ---- epilogue ----
    const int er0 = bm + warp_m * 32 + gid;
    const int ec0 = warp_n * 64 + (tig << 1);
#pragma unroll
    for (int mt = 0; mt < 2; mt++) {
#pragma unroll
        for (int half = 0; half < 2; half++) {
            int row = er0 + mt * 16 + half * 8;
            if (row >= M) continue;
#pragma unroll
            for (int nt = 0; nt < 8; nt++) {
                int col = ec0 + nt * 8;
                float v0 = c[mt][nt][half * 2 + 0];
                float v1 = c[mt][nt][half * 2 + 1];
                if (EPI == 1 && bias) { v0 += bias[col]; v1 += bias[col + 1]; }
                if (EPI == 0) {
                    *(float2*)(Cf + (size_t)row * HH + col) = make_float2(v0, v1);
                } else if (EPI == 1) {
                    uint32_t hp, lp; split2(v0, v1, hp, lp);
                    Chi[(size_t)row * KW_H + (col >> 1)] = hp;
                    Clo[(size_t)row * KW_H + (col >> 1)] = lp;
                } else {
                    if (by < 8)
                        *(float2*)(Cf + (size_t)row * (RR * HH) + by * HH + col) = make_float2(v0, v1);
                    else
                        *(float2*)(Cagg + (size_t)row * HH + col) = make_float2(v0, v1);
                }
            }
        }
    }
}

// ---------------- degree + scatter + layer-finalize ----------------
__global__ void deg_count(const int* __restrict__ tgt, const int* __restrict__ et,
                          float* __restrict__ deg, int E) {
    int e = blockIdx.x * blockDim.x + threadIdx.x;
    if (e >= E) return;
    atomicAdd(deg + (size_t)tgt[e] * RR + et[e], 1.0f);
}

__global__ void make_invdeg(float* deg, int n) {
    int i = blockIdx.x * blockDim.x + threadIdx.x;
    if (i < n) deg[i] = 1.0f / fmaxf(deg[i], 1.0f);
}

// warp per edge: agg[tgt] += Y[src, etype] * invdeg[tgt, etype]
__global__ void scatter_edges(const int* __restrict__ src, const int* __restrict__ tgt,
                              const int* __restrict__ et, const float* __restrict__ Y,
                              const float* __restrict__ invdeg, float* __restrict__ agg, int E)
{
    int w = (blockIdx.x * blockDim.x + threadIdx.x) >> 5;
    int lane = threadIdx.x & 31;
    if (w >= E) return;
    int s = src[w], t = tgt[w], r = et[w];
    float iv = invdeg[(size_t)t * RR + r];
    float4 v = ((const float4*)(Y + (size_t)s * (RR * HH) + r * HH))[lane];
    red4(agg + (size_t)t * HH + lane * 4, v.x * iv, v.y * iv, v.z * iv, v.w * iv);
}

// h_next = relu(agg + b) -> packed hi/lo
__global__ void layer_fin(const float* __restrict__ agg, const float* __restrict__ b,
                          uint32_t* __restrict__ dhi, uint32_t* __restrict__ dlo, int nwords)
{
    int i = blockIdx.x * blockDim.x + threadIdx.x;
    if (i >= nwords) return;
    int col2 = (i & (KW_H - 1)) << 1;
    float2 v = ((const float2*)agg)[i];
    float v0 = fmaxf(v.x + b[col2], 0.f);
    float v1 = fmaxf(v.y + b[col2 + 1], 0.f);
    uint32_t hp, lp; split2(v0, v1, hp, lp);
    dhi[i] = hp; dlo[i] = lp;
}

// ---------------- GAT ----------------
__global__ void att_node(const float* __restrict__ z, const float* __restrict__ att,
                         float* __restrict__ asrc, float* __restrict__ atgt, int n)
{
    int i = blockIdx.x * blockDim.x + threadIdx.x;
    if (i >= n * HEADS) return;
    int node = i >> 3, hd = i & 7;
    const float* zp = z + (size_t)node * HH + hd * DHH;
    const float* al = att + hd * (2 * DHH);
    float sa = 0.f, sb = 0.f;
#pragma unroll
    for (int d = 0; d < DHH; d++) {
        float zv = zp[d];
        sa += zv * al[d];
        sb += zv * al[DHH + d];
    }
    asrc[i] = sa;
    atgt[i] = sb;
}

__global__ void gat_pass1(const int* __restrict__ src, const int* __restrict__ tgt,
                          const float* __restrict__ asrc, const float* __restrict__ atgt,
                          float* __restrict__ alpha, unsigned* __restrict__ amax, int E)
{
    int e = blockIdx.x * blockDim.x + threadIdx.x;
    if (e >= E) return;
    int s = src[e], t = tgt[e];
    float4 s0 = ((const float4*)(asrc + (size_t)s * HEADS))[0];
    float4 s1 = ((const float4*)(asrc + (size_t)s * HEADS))[1];
    float4 t0 = ((const float4*)(atgt + (size_t)t * HEADS))[0];
    float4 t1 = ((const float4*)(atgt + (size_t)t * HEADS))[1];
    float a[8] = { s0.x + t0.x, s0.y + t0.y, s0.z + t0.z, s0.w + t0.w,
                   s1.x + t1.x, s1.y + t1.y, s1.z + t1.z, s1.w + t1.w };
#pragma unroll
    for (int hd = 0; hd < 8; hd++) a[hd] = a[hd] > 0.f ? a[hd] : 0.2f * a[hd];
    ((float4*)(alpha + (size_t)e * HEADS))[0] = make_float4(a[0], a[1], a[2], a[3]);
    ((float4*)(alpha + (size_t)e * HEADS))[1] = make_float4(a[4], a[5], a[6], a[7]);
#pragma unroll
    for (int hd = 0; hd < 8; hd++) atomicMax(amax + (size_t)t * HEADS + hd, enc_f(a[hd]));
}

__global__ void gat_pass2(const int* __restrict__ src, const int* __restrict__ tgt,
                          const float* __restrict__ alpha, const unsigned* __restrict__ amax,
                          const float* __restrict__ z, float* __restrict__ denom,
                          float* __restrict__ outun, int E)
{
    int w = (blockIdx.x * blockDim.x + threadIdx.x) >> 5;
    int lane = threadIdx.x & 31;
    if (w >= E) return;
    int s = src[w], t = tgt[w];
    int head = lane >> 2;
    float al = alpha[(size_t)w * HEADS + head];
    float am = dec_f(amax[(size_t)t * HEADS + head]);
    float ex = __expf(al - am);
    if ((lane & 3) == 0) atomicAdd(denom + (size_t)t * HEADS + head, ex);
    float4 zv = ((const float4*)(z + (size_t)s * HH))[lane];
    red4(outun + (size_t)t * HH + lane * 4, zv.x * ex, zv.y * ex, zv.z * ex, zv.w * ex);
}

// finalize: gat-normalize + bg, then 128x3 projection, log_softmax. Warp per node.
__global__ void finalize(const float* __restrict__ outun, const float* __restrict__ denom,
                         const float* __restrict__ bg, const float* __restrict__ Wf,
                         const float* __restrict__ bf, float* __restrict__ out, int n)
{
    int w = (blockIdx.x * blockDim.x + threadIdx.x) >> 5;
    int lane = threadIdx.x & 31;
    if (w >= n) return;
    float4 g = ((const float4*)(outun + (size_t)w * HH))[lane];
    int head = lane >> 2;
    float dn = denom[(size_t)w * HEADS + head];
    float inv = 1.0f / fmaxf(dn, 1e-16f);
    float4 bgv = ((const float4*)bg)[lane];
    float gv[4] = { g.x * inv + bgv.x, g.y * inv + bgv.y,
                    g.z * inv + bgv.z, g.w * inv + bgv.w };
    float a0 = 0.f, a1 = 0.f, a2 = 0.f;
    int j0 = lane * 4;
#pragma unroll
    for (int c = 0; c < 4; c++) {
        int j = j0 + c;
        a0 += gv[c] * Wf[j * OUTC + 0];
        a1 += gv[c] * Wf[j * OUTC + 1];
        a2 += gv[c] * Wf[j * OUTC + 2];
    }
#pragma unroll
    for (int off = 16; off > 0; off >>= 1) {
        a0 += __shfl_xor_sync(0xFFFFFFFFu, a0, off);
        a1 += __shfl_xor_sync(0xFFFFFFFFu, a1, off);
        a2 += __shfl_xor_sync(0xFFFFFFFFu, a2, off);
    }
    if (lane == 0) {
        float l0 = a0 + bf[0], l1 = a1 + bf[1], l2 = a2 + bf[2];
        float m = fmaxf(l0, fmaxf(l1, l2));
        float lse = m + logf(expf(l0 - m) + expf(l1 - m) + expf(l2 - m));
        out[(size_t)w * OUTC + 0] = l0 - lse;
        out[(size_t)w * OUTC + 1] = l1 - lse;
        out[(size_t)w * OUTC + 2] = l2 - lse;
    }
}

// ---------------- launch ----------------
extern "C" void kernel_launch(void* const* d_in, const int* in_sizes, int n_in,
                              void* d_out, int out_size)
{
    const float* x     = (const float*)d_in[0];
    const int*   ei    = (const int*)d_in[1];
    const int*   etype = (const int*)d_in[2];
    const float* Wp    = (const float*)d_in[3];
    const float* bp    = (const float*)d_in[4];
    const float* W1    = (const float*)d_in[5];
    const float* root1 = (const float*)d_in[6];
    const float* b1    = (const float*)d_in[7];
    const float* W2    = (const float*)d_in[8];
    const float* root2 = (const float*)d_in[9];
    const float* b2    = (const float*)d_in[10];
    const float* Wg    = (const float*)d_in[11];
    const float* att   = (const float*)d_in[12];
    const float* bg    = (const float*)d_in[13];
    const float* Wf    = (const float*)d_in[14];
    const float* bf    = (const float*)d_in[15];
    float* out = (float*)d_out;

    const int* src = ei;
    const int* tgt = ei + EE;

    float *Y, *agg, *z, *deg, *asrc, *atgt, *denom, *alpha, *outun;
    uint32_t *xhi, *xlo, *hAhi, *hAlo, *hBhi, *hBlo;
    uint32_t *w1hi, *w1lo, *w2hi, *w2lo, *wphi, *wplo, *wghi, *wglo;
    unsigned* amax;
    cudaGetSymbolAddress((void**)&Y, g_Y);
    cudaGetSymbolAddress((void**)&agg, g_agg);
    cudaGetSymbolAddress((void**)&z, g_z);
    cudaGetSymbolAddress((void**)&deg, g_deg);
    cudaGetSymbolAddress((void**)&asrc, g_asrc);
    cudaGetSymbolAddress((void**)&atgt, g_atgt);
    cudaGetSymbolAddress((void**)&denom, g_denom);
    cudaGetSymbolAddress((void**)&alpha, g_alpha);
    cudaGetSymbolAddress((void**)&outun, g_outun);
    cudaGetSymbolAddress((void**)&amax, g_amax);
    cudaGetSymbolAddress((void**)&xhi, g_xhi);
    cudaGetSymbolAddress((void**)&xlo, g_xlo);
    cudaGetSymbolAddress((void**)&hAhi, g_hAhi);
    cudaGetSymbolAddress((void**)&hAlo, g_hAlo);
    cudaGetSymbolAddress((void**)&hBhi, g_hBhi);
    cudaGetSymbolAddress((void**)&hBlo, g_hBlo);
    cudaGetSymbolAddress((void**)&w1hi, g_w1hi);
    cudaGetSymbolAddress((void**)&w1lo, g_w1lo);
    cudaGetSymbolAddress((void**)&w2hi, g_w2hi);
    cudaGetSymbolAddress((void**)&w2lo, g_w2lo);
    cudaGetSymbolAddress((void**)&wphi, g_wphi);
    cudaGetSymbolAddress((void**)&wplo, g_wplo);
    cudaGetSymbolAddress((void**)&wghi, g_wghi);
    cudaGetSymbolAddress((void**)&wglo, g_wglo);

    const int gemmGrid = (NN + 127) / 128;   // 391
    const int scatGrid = (EE + 7) / 8;

    // ---- one-time packs / splits / degrees ----
    {
        dim3 g1((KW_H * HH + 255) / 256, 9);
        pack_b<<<g1, 256>>>(W1, root1, w1hi, w1lo, KW_H);
        pack_b<<<g1, 256>>>(W2, root2, w2hi, w2lo, KW_H);
        dim3 g2((KW_X * HH + 255) / 256, 1);
        pack_b<<<g2, 256>>>(Wp, nullptr, wphi, wplo, KW_X);
        dim3 g3((KW_H * HH + 255) / 256, 1);
        pack_b<<<g3, 256>>>(Wg, nullptr, wghi, wglo, KW_H);
    }
    split_mat<<<(NN * KW_X + 255) / 256, 256>>>(x, xhi, xlo, NN * KW_X);
    fill_f4<<<64, 256>>>((float4*)deg, NN * RR / 4, 0.f);
    deg_count<<<(EE + 255) / 256, 256>>>(tgt, etype, deg, EE);
    make_invdeg<<<(NN * RR + 255) / 256, 256>>>(deg, NN * RR);

    // ---- projection: hA = pack(x @ Wp + bp)
    gemm_pk<1><<<dim3(gemmGrid, 1), 256>>>(xhi, xlo, wphi, wplo, bp,
                                           nullptr, nullptr, hAhi, hAlo, NN, KW_X);

    // ---- RGCN layer 1 ----
    gemm_pk<2><<<dim3(gemmGrid, 9), 256>>>(hAhi, hAlo, w1hi, w1lo, nullptr,
                                           Y, agg, nullptr, nullptr, NN, KW_H);
    scatter_edges<<<scatGrid, 256>>>(src, tgt, etype, Y, deg, agg, EE);
    layer_fin<<<(NN * KW_H + 255) / 256, 256>>>(agg, b1, hBhi, hBlo, NN * KW_H);

    // ---- RGCN layer 2 ----
    gemm_pk<2><<<dim3(gemmGrid, 9), 256>>>(hBhi, hBlo, w2hi, w2lo, nullptr,
                                           Y, agg, nullptr, nullptr, NN, KW_H);
    scatter_edges<<<scatGrid, 256>>>(src, tgt, etype, Y, deg, agg, EE);
    layer_fin<<<(NN * KW_H + 255) / 256, 256>>>(agg, b2, hAhi, hAlo, NN * KW_H);

    // ---- GAT ----
    gemm_pk<0><<<dim3(gemmGrid, 1), 256>>>(hAhi, hAlo, wghi, wglo, nullptr,
                                           z, nullptr, nullptr, nullptr, NN, KW_H);
    att_node<<<(NN * HEADS + 255) / 256, 256>>>(z, att, asrc, atgt, NN);
    fill_u4<<<64, 256>>>((uint4*)amax, NN * HEADS / 4, ENC_NEG_INF);
    fill_f4<<<64, 256>>>((float4*)denom, NN * HEADS / 4, 0.f);
    fill_f4<<<512, 256>>>((float4*)outun, NN * HH / 4, 0.f);
    gat_pass1<<<(EE + 255) / 256, 256>>>(src, tgt, asrc, atgt, alpha, amax, EE);
    gat_pass2<<<scatGrid, 256>>>(src, tgt, alpha, amax, z, denom, outun, EE);

    // ---- finalize
    finalize<<<(NN + 7) / 8, 256>>>(outun, denom, bg, Wf, bf, out, NN);
}